// round 12
// baseline (speedup 1.0000x reference)
#include <cuda_runtime.h>
#include <cuda_bf16.h>
#include <cstdint>

// Fixed shapes: B=1, L=1024, C_Z=128, C_S=1024, C_S_OUT=1024
#define PADA 136            // bf16 elems per smem row (128 + 8 pad), ldmatrix conflict-free
#define NLB  16
#define LBSZ 64

// smem layout (bytes) for pair kernel
#define OFF_W1G  0          // 128 x PADA bf16 = 34816
#define OFF_A    34816      // 128 x PADA bf16 = 34816 (single buffer)
#define OFF_Z    69632      // 128 x 132 f32 = 67584 (cp.async stage)
#define OFF_V    137216     // 128 x 132 f32 = 67584
#define OFF_PQ   204800     // 128 float2 = 1024
#define OFF_MSK  205824     // 128 f32 = 512
#define OFF_UV   206336     // 128 float2 = 1024
#define OFF_PART 207360     // 256 f32 = 1024
#define SMEM_PAIR 208384

// ---------------- device scratch ----------------
__device__ float g_scratch_c[8ull  * 1024ull * 128ull];   // [m_block][l][k]
__device__ float g_scratch_r[16ull * 1024ull * 128ull];   // [l_block][m][k]
__device__ float g_catf[1024ull * 1280ull];
__device__ float g_norm_c[1024];
__device__ float g_norm_r[1024];
__device__ float g_u[128];
__device__ float g_v[128];

// ---------------- helpers ----------------
__device__ __forceinline__ void ldsm4(uint32_t &r0, uint32_t &r1, uint32_t &r2, uint32_t &r3, uint32_t addr) {
    asm volatile("ldmatrix.sync.aligned.m8n8.x4.shared.b16 {%0,%1,%2,%3}, [%4];"
                 : "=r"(r0), "=r"(r1), "=r"(r2), "=r"(r3) : "r"(addr));
}
__device__ __forceinline__ void mma_bf16(float* d, uint32_t a0, uint32_t a1, uint32_t a2, uint32_t a3,
                                         uint32_t b0, uint32_t b1) {
    asm volatile("mma.sync.aligned.m16n8k16.row.col.f32.bf16.bf16.f32 "
                 "{%0,%1,%2,%3}, {%4,%5,%6,%7}, {%8,%9}, {%0,%1,%2,%3};"
                 : "+f"(d[0]), "+f"(d[1]), "+f"(d[2]), "+f"(d[3])
                 : "r"(a0), "r"(a1), "r"(a2), "r"(a3), "r"(b0), "r"(b1));
}
__device__ __forceinline__ void mma_tf32(float* d, uint32_t a0, uint32_t a1, uint32_t a2, uint32_t a3,
                                         uint32_t b0, uint32_t b1) {
    asm volatile("mma.sync.aligned.m16n8k8.row.col.f32.tf32.tf32.f32 "
                 "{%0,%1,%2,%3}, {%4,%5,%6,%7}, {%8,%9}, {%0,%1,%2,%3};"
                 : "+f"(d[0]), "+f"(d[1]), "+f"(d[2]), "+f"(d[3])
                 : "r"(a0), "r"(a1), "r"(a2), "r"(a3), "r"(b0), "r"(b1));
}
__device__ __forceinline__ uint32_t f2tf(float f) {
    uint32_t r; asm("cvt.rna.tf32.f32 %0, %1;" : "=r"(r) : "f"(f)); return r;
}
__device__ __forceinline__ uint32_t pack_bf2(float a, float b) {
    __nv_bfloat162 t = __floats2bfloat162_rn(a, b);
    return *reinterpret_cast<uint32_t*>(&t);
}
__device__ __forceinline__ void cpa16(uint32_t dst, const void* src) {
    asm volatile("cp.async.cg.shared.global [%0], [%1], 16;" :: "r"(dst), "l"(src));
}

// ---------------- K0: norms + (u,v) precompute ----------------
__global__ void norm_kernel(const float* __restrict__ mask, const float* __restrict__ w1,
                            const float* __restrict__ lng, const float* __restrict__ lnb,
                            const float* __restrict__ b1) {
    if (blockIdx.x == 8) {          // u[d] = W1[d,:]·g ; v[d] = W1[d,:]·b + b1[d]
        int d = threadIdx.x;
        if (d < 128) {
            const float* wrow = w1 + (size_t)d * 128;
            float u = 0.f, v = 0.f;
#pragma unroll 8
            for (int c = 0; c < 128; c++) {
                float wv = wrow[c];
                u = fmaf(wv, lng[c], u);
                v = fmaf(wv, lnb[c], v);
            }
            g_u[d] = u;
            g_v[d] = v + b1[d];
        }
        return;
    }
    int t = blockIdx.x * 256 + threadIdx.x;
    if (t < 1024) {
        float s = 0.f;
#pragma unroll 8
        for (int l = 0; l < 1024; l++) s += mask[(size_t)l * 1024 + t];
        g_norm_r[t] = s;
    } else {
        int l = t - 1024;
        const float4* p = (const float4*)(mask + (size_t)l * 1024);
        float s = 0.f;
#pragma unroll 8
        for (int m = 0; m < 256; m++) { float4 v = p[m]; s += v.x + v.y + v.z + v.w; }
        g_norm_c[l] = s;
    }
}

// ---------------- K1: pair kernel (HMMA, LN folded, B-in-regs, cp.async pipeline) ----------------
__global__ __launch_bounds__(256, 1)
void pair_kernel(const float* __restrict__ z, const float* __restrict__ mask,
                 const float* __restrict__ w1, const float* __restrict__ lng) {
    extern __shared__ char sm[];
    __nv_bfloat16* w1s = (__nv_bfloat16*)(sm + OFF_W1G);
    float*  zstage = (float*)(sm + OFF_Z);
    float*  V    = (float*)(sm + OFF_V);
    float2* pqs  = (float2*)(sm + OFF_PQ);
    float*  mskb = (float*)(sm + OFF_MSK);
    float2* uvs  = (float2*)(sm + OFF_UV);
    float*  part = (float*)(sm + OFF_PART);

    const int tid  = threadIdx.x;
    const int w    = tid >> 5;
    const int lane = tid & 31;
    const int g    = lane >> 2;
    const int tc   = lane & 3;
    const int mb   = blockIdx.x;            // 0..7
    const int lb   = blockIdx.y;            // 0..15
    const int m0   = mb * 128;
    const int r_ld = tid >> 1;              // row 0..127 (copy/convert mapping)
    const int h_ld = tid & 1;               // half-row

    const uint32_t smem_u = (uint32_t)__cvta_generic_to_shared(sm);
    const uint32_t zs_u   = smem_u + OFF_Z;
    const uint32_t msk_u  = smem_u + OFF_MSK;

    // ---- fill W1g tile (bf16, PADA layout, rows = d, cols = c) ----
    for (int i = tid; i < 128 * 128; i += 256) {
        int r = i >> 7, c = i & 127;
        w1s[r * PADA + c] = __float2bfloat16(w1[i] * lng[c]);
    }
    if (tid < 128) uvs[tid] = make_float2(g_u[tid], g_v[tid]);

    // ---- issue first z tile + mask via cp.async ----
    {
        int l0 = lb * LBSZ;
        const float* zsrc = z + ((size_t)l0 * 1024 + m0 + r_ld) * 128 + h_ld * 64;
        uint32_t zdst = zs_u + (uint32_t)((r_ld * 132 + h_ld * 64) * 4);
#pragma unroll
        for (int j = 0; j < 16; j++) cpa16(zdst + j * 16, zsrc + j * 4);
        if (tid < 32) cpa16(msk_u + tid * 16, mask + (size_t)l0 * 1024 + m0 + tid * 4);
        asm volatile("cp.async.commit_group;");
    }

    // per-lane ldmatrix offsets (proven mapping)
    const int lane7 = lane & 7;
    const int a_row = (((lane >> 3) & 1) << 3) + lane7;
    const int a_col = ((lane >> 4) & 1) << 3;
    const int b_row = (((lane >> 4) & 1) << 3) + lane7;
    const int b_col = ((lane >> 3) & 1) << 3;

    const uint32_t at_u = smem_u + OFF_A;
    const uint32_t w1_u = smem_u + OFF_W1G;

    __syncthreads();   // W1g visible

    // ---- preload B fragments for this warp's 16-col n-slice (held all kernel) ----
    uint32_t bfr[32];
    {
        uint32_t bb = w1_u + (uint32_t)(((w * 16 + b_row) * PADA + b_col) * 2);
#pragma unroll
        for (int k = 0; k < 8; k++)
            ldsm4(bfr[4 * k], bfr[4 * k + 1], bfr[4 * k + 2], bfr[4 * k + 3], bb + k * 32);
    }

    float acc_l[64];
#pragma unroll
    for (int i = 0; i < 64; i++) acc_l[i] = 0.f;

    for (int i = 0; i < LBSZ; ++i) {
        const int l = lb * LBSZ + i;

        // ---- wait own cp.async data; convert zstage -> A (raw bf16) + stats ----
        asm volatile("cp.async.wait_group 0;");
        {
            const float* zrow = zstage + r_ld * 132 + h_ld * 64;
            char* dst = sm + OFF_A + (size_t)(r_ld * PADA + h_ld * 64) * 2;
            float s = 0.f, sq = 0.f;
#pragma unroll
            for (int c4 = 0; c4 < 4; c4++) {
                float4 v0 = *(const float4*)(zrow + c4 * 16);
                float4 v1 = *(const float4*)(zrow + c4 * 16 + 4);
                float4 v2 = *(const float4*)(zrow + c4 * 16 + 8);
                float4 v3 = *(const float4*)(zrow + c4 * 16 + 12);
                s += v0.x + v0.y + v0.z + v0.w + v1.x + v1.y + v1.z + v1.w
                   + v2.x + v2.y + v2.z + v2.w + v3.x + v3.y + v3.z + v3.w;
                sq = fmaf(v0.x, v0.x, sq); sq = fmaf(v0.y, v0.y, sq);
                sq = fmaf(v0.z, v0.z, sq); sq = fmaf(v0.w, v0.w, sq);
                sq = fmaf(v1.x, v1.x, sq); sq = fmaf(v1.y, v1.y, sq);
                sq = fmaf(v1.z, v1.z, sq); sq = fmaf(v1.w, v1.w, sq);
                sq = fmaf(v2.x, v2.x, sq); sq = fmaf(v2.y, v2.y, sq);
                sq = fmaf(v2.z, v2.z, sq); sq = fmaf(v2.w, v2.w, sq);
                sq = fmaf(v3.x, v3.x, sq); sq = fmaf(v3.y, v3.y, sq);
                sq = fmaf(v3.z, v3.z, sq); sq = fmaf(v3.w, v3.w, sq);
                uint4 pk0, pk1;
                pk0.x = pack_bf2(v0.x, v0.y); pk0.y = pack_bf2(v0.z, v0.w);
                pk0.z = pack_bf2(v1.x, v1.y); pk0.w = pack_bf2(v1.z, v1.w);
                pk1.x = pack_bf2(v2.x, v2.y); pk1.y = pack_bf2(v2.z, v2.w);
                pk1.z = pack_bf2(v3.x, v3.y); pk1.w = pack_bf2(v3.z, v3.w);
                *(uint4*)(dst + c4 * 32)      = pk0;
                *(uint4*)(dst + c4 * 32 + 16) = pk1;
            }
            s  += __shfl_xor_sync(0xffffffffu, s, 1);
            sq += __shfl_xor_sync(0xffffffffu, sq, 1);
            float mu  = s * (1.f / 128.f);
            float var = fmaf(sq, 1.f / 128.f, -mu * mu);
            float rs  = rsqrtf(var + 1e-5f);
            if (h_ld == 0) pqs[r_ld] = make_float2(rs, rs * mu);
        }
        __syncthreads();   // A + pqs + mask visible; zstage consumed

        // ---- issue next tile into zstage (fire & forget, overlaps GEMM) ----
        if (i + 1 < LBSZ) {
            const float* zsrc = z + ((size_t)(l + 1) * 1024 + m0 + r_ld) * 128 + h_ld * 64;
            uint32_t zdst = zs_u + (uint32_t)((r_ld * 132 + h_ld * 64) * 4);
#pragma unroll
            for (int j = 0; j < 16; j++) cpa16(zdst + j * 16, zsrc + j * 4);
            if (tid < 32) cpa16(msk_u + tid * 16, mask + (size_t)(l + 1) * 1024 + m0 + tid * 4);
            asm volatile("cp.async.commit_group;");
        }

        // mask values for epilogue must be read BEFORE next cp.async overwrites mskb —
        // but cp.async data only lands later; reads below use the barrier-protected copy.
        // (cp.async writes complete only at next wait_group; no ordering hazard within this iter.)

        // ---- GEMM: acc(M128 x n16-slice) = A @ W1g^T ----
        float acc[64];
#pragma unroll
        for (int j = 0; j < 64; j++) acc[j] = 0.f;
#pragma unroll
        for (int mt = 0; mt < 8; mt++) {
            uint32_t abase = at_u + (uint32_t)(((mt * 16 + a_row) * PADA + a_col) * 2);
#pragma unroll
            for (int k = 0; k < 8; k++) {
                uint32_t a0, a1, a2, a3;
                ldsm4(a0, a1, a2, a3, abase + k * 32);
                mma_bf16(acc + mt * 8,     a0, a1, a2, a3, bfr[4 * k],     bfr[4 * k + 1]);
                mma_bf16(acc + mt * 8 + 4, a0, a1, a2, a3, bfr[4 * k + 2], bfr[4 * k + 3]);
            }
        }

        // ---- combine previous iteration's column partials ----
        if (i > 0 && tid < 128)
            g_scratch_c[((size_t)mb * 1024 + (l - 1)) * 128 + tid] = part[tid] + part[128 + tid];

        // ---- epilogue: y = p*G - q*u + v ; relu ; *mask ; acc_l += ; V stash ----
#pragma unroll
        for (int mt = 0; mt < 8; mt++) {
            int rlo = mt * 16 + g, rhi = rlo + 8;
            float2 pq0 = pqs[rlo], pq1 = pqs[rhi];
            float mk0 = mskb[rlo], mk1 = mskb[rhi];
#pragma unroll
            for (int nt = 0; nt < 2; nt++) {
                int c0 = w * 16 + nt * 8 + tc * 2;
                float2 uvA = uvs[c0], uvB = uvs[c0 + 1];
                int id = mt * 8 + nt * 4;
                float t0 = fmaxf(fmaf(pq0.x, acc[id],     fmaf(-pq0.y, uvA.x, uvA.y)), 0.f) * mk0;
                float t1 = fmaxf(fmaf(pq0.x, acc[id + 1], fmaf(-pq0.y, uvB.x, uvB.y)), 0.f) * mk0;
                float t2 = fmaxf(fmaf(pq1.x, acc[id + 2], fmaf(-pq1.y, uvA.x, uvA.y)), 0.f) * mk1;
                float t3 = fmaxf(fmaf(pq1.x, acc[id + 3], fmaf(-pq1.y, uvB.x, uvB.y)), 0.f) * mk1;
                acc_l[id] += t0; acc_l[id + 1] += t1; acc_l[id + 2] += t2; acc_l[id + 3] += t3;
                *(float2*)(V + rlo * 132 + c0) = make_float2(t0, t1);
                *(float2*)(V + rhi * 132 + c0) = make_float2(t2, t3);
            }
        }
        __syncthreads();   // V complete

        // ---- column sums over m (half-columns, conflict-free) ----
        {
            int c = tid & 127, half = tid >> 7;
            const float* p = V + half * 64 * 132 + c;
            float s = 0.f;
#pragma unroll 16
            for (int r = 0; r < 64; r++) s += p[r * 132];
            part[half * 128 + c] = s;
        }
        // no barrier: part consumed after next iteration's barrier
    }

    __syncthreads();
    if (tid < 128)
        g_scratch_c[((size_t)mb * 1024 + (lb * LBSZ + LBSZ - 1)) * 128 + tid] = part[tid] + part[128 + tid];

    // ---- over-l partials -> g_scratch_r ----
#pragma unroll
    for (int mt = 0; mt < 8; mt++) {
        int rl = m0 + mt * 16 + g;
#pragma unroll
        for (int nt = 0; nt < 2; nt++) {
            int c0 = w * 16 + nt * 8 + tc * 2;
            int id = mt * 8 + nt * 4;
            *(float2*)&g_scratch_r[((size_t)lb * 1024 + rl)     * 128 + c0] =
                make_float2(acc_l[id], acc_l[id + 1]);
            *(float2*)&g_scratch_r[((size_t)lb * 1024 + rl + 8) * 128 + c0] =
                make_float2(acc_l[id + 2], acc_l[id + 3]);
        }
    }
}

// ---------------- K2: reduce partials, deferred GEMM2, build concat ----------------
__global__ __launch_bounds__(256, 4)
void cat_kernel(const float* __restrict__ s_s_in, const float* __restrict__ w2,
                const float* __restrict__ b2) {
    __shared__ alignas(16) float Sc[128];
    __shared__ alignas(16) float Sr[128];
    int l = blockIdx.x;
    int t = threadIdx.x;
    if (t < 128) {
        float s = 0.f;
#pragma unroll
        for (int p = 0; p < 8; p++) s += g_scratch_c[((size_t)p * 1024 + l) * 128 + t];
        Sc[t] = s;
    } else {
        int c = t - 128;
        float s = 0.f;
#pragma unroll
        for (int p = 0; p < 16; p++) s += g_scratch_r[((size_t)p * 1024 + l) * 128 + c];
        Sr[c] = s;
    }
    __syncthreads();

    int c = t & 127;
    const float4* wrow = (const float4*)(w2 + (size_t)c * 128);
    const float4* Sv   = (const float4*)((t < 128) ? Sc : Sr);
    float s = 0.f;
#pragma unroll 8
    for (int kk = 0; kk < 32; kk++) {
        float4 wv = wrow[kk], sv = Sv[kk];
        s = fmaf(wv.x, sv.x, s); s = fmaf(wv.y, sv.y, s);
        s = fmaf(wv.z, sv.z, s); s = fmaf(wv.w, sv.w, s);
    }
    float ns = (t < 128) ? g_norm_c[l] : g_norm_r[l];
    float val = (s + ns * b2[c]) / fmaxf(ns, 1.f);
    g_catf[(size_t)l * 1280 + ((t < 128) ? 0 : 128) + c] = val;

    for (int cc = t; cc < 1024; cc += 256)
        g_catf[(size_t)l * 1280 + 256 + cc] = s_s_in[(size_t)l * 1024 + cc];
}

// ---------------- K3: final projection (tf32), 32-row tiles, 256 CTAs ----------------
#define PADF 36
__global__ __launch_bounds__(256, 2)
void final_gemm(const float* __restrict__ wc, const float* __restrict__ bc, float* __restrict__ out) {
    __shared__ uint32_t atf[32 * PADF];
    __shared__ uint32_t btf[128 * PADF];
    const int tid = threadIdx.x, w = tid >> 5, lane = tid & 31;
    const int g = lane >> 2, tc = lane & 3;
    const int wr = w & 1, cg = w >> 1;        // wr: m-tile (16 rows), cg: 32-col group
    const int l0 = blockIdx.y * 32, d0 = blockIdx.x * 128;
    const int q = tid & 7, rload = tid >> 3;  // rload 0..31

    float d[16];
#pragma unroll
    for (int i = 0; i < 16; i++) d[i] = 0.f;

    float4 va, vb0, vb1, vb2, vb3;
    auto ldg = [&](int kc) {
        int k0 = kc * 32 + q * 4;
        va  = *(const float4*)(g_catf + (size_t)(l0 + rload) * 1280 + k0);
        vb0 = *(const float4*)(wc + (size_t)(d0 + rload)      * 1280 + k0);
        vb1 = *(const float4*)(wc + (size_t)(d0 + rload + 32) * 1280 + k0);
        vb2 = *(const float4*)(wc + (size_t)(d0 + rload + 64) * 1280 + k0);
        vb3 = *(const float4*)(wc + (size_t)(d0 + rload + 96) * 1280 + k0);
    };
    auto stv = [&](uint32_t* base, int r, float4 v) {
        uint32_t* p = base + r * PADF + q;
        p[0] = f2tf(v.x); p[8] = f2tf(v.y); p[16] = f2tf(v.z); p[24] = f2tf(v.w);
    };

    ldg(0);
    for (int kc = 0; kc < 40; ++kc) {
        __syncthreads();
        stv(atf, rload, va);
        stv(btf, rload,      vb0); stv(btf, rload + 32, vb1);
        stv(btf, rload + 64, vb2); stv(btf, rload + 96, vb3);
        if (kc + 1 < 40) ldg(kc + 1);
        __syncthreads();

        uint32_t aw0[8], aw1[8];
        *(uint4*)(aw0)     = *(uint4*)&atf[(16 * wr + g)     * PADF + tc * 8];
        *(uint4*)(aw0 + 4) = *(uint4*)&atf[(16 * wr + g)     * PADF + tc * 8 + 4];
        *(uint4*)(aw1)     = *(uint4*)&atf[(16 * wr + 8 + g) * PADF + tc * 8];
        *(uint4*)(aw1 + 4) = *(uint4*)&atf[(16 * wr + 8 + g) * PADF + tc * 8 + 4];
#pragma unroll
        for (int nt = 0; nt < 4; nt++) {
            int rowb = cg * 32 + nt * 8 + g;
            uint32_t bw[8];
            *(uint4*)(bw)     = *(uint4*)&btf[rowb * PADF + tc * 8];
            *(uint4*)(bw + 4) = *(uint4*)&btf[rowb * PADF + tc * 8 + 4];
#pragma unroll
            for (int kp = 0; kp < 4; kp++)
                mma_tf32(d + nt * 4, aw0[2 * kp], aw1[2 * kp], aw0[2 * kp + 1], aw1[2 * kp + 1],
                         bw[2 * kp], bw[2 * kp + 1]);
        }
    }

    int row = l0 + 16 * wr + g;
#pragma unroll
    for (int nt = 0; nt < 4; nt++) {
        int col = d0 + cg * 32 + nt * 8 + tc * 2;
        float bb0 = bc[col], bb1 = bc[col + 1];
        *(float2*)&out[(size_t)row * 1024 + col]       = make_float2(d[nt * 4 + 0] + bb0, d[nt * 4 + 1] + bb1);
        *(float2*)&out[(size_t)(row + 8) * 1024 + col] = make_float2(d[nt * 4 + 2] + bb0, d[nt * 4 + 3] + bb1);
    }
}

// ---------------- launch ----------------
extern "C" void kernel_launch(void* const* d_in, const int* in_sizes, int n_in,
                              void* d_out, int out_size) {
    const float* s_z    = (const float*)d_in[0];
    const float* s_s_in = (const float*)d_in[1];
    const float* mask   = (const float*)d_in[2];
    const float* ln_g   = (const float*)d_in[3];
    const float* ln_b   = (const float*)d_in[4];
    const float* w1     = (const float*)d_in[5];
    const float* b1     = (const float*)d_in[6];
    const float* w2     = (const float*)d_in[7];
    const float* b2     = (const float*)d_in[8];
    const float* wc     = (const float*)d_in[9];
    const float* bc     = (const float*)d_in[10];
    float* out = (float*)d_out;

    cudaFuncSetAttribute(pair_kernel, cudaFuncAttributeMaxDynamicSharedMemorySize, SMEM_PAIR);

    norm_kernel<<<9, 256>>>(mask, w1, ln_g, ln_b, b1);
    pair_kernel<<<dim3(8, NLB), 256, SMEM_PAIR>>>(s_z, mask, w1, ln_g);
    cat_kernel<<<1024, 256>>>(s_s_in, w2, b2);
    final_gemm<<<dim3(8, 32), 256>>>(wc, bc, out);
}

// round 15
// speedup vs baseline: 1.1016x; 1.1016x over previous
#include <cuda_runtime.h>
#include <cuda_bf16.h>
#include <cstdint>

// Fixed shapes: B=1, L=1024, C_Z=128, C_S=1024, C_S_OUT=1024
#define PADA 136            // bf16 elems per smem row (128 + 8 pad), ldmatrix conflict-free
#define NLB  16
#define LBSZ 64

// smem layout (bytes) for pair kernel
#define OFF_W1G  0          // 128 x PADA bf16 = 34816
#define OFF_A    34816      // 128 x PADA bf16 = 34816 (single buffer)
#define OFF_Z    69632      // 2 x 128 x 132 f32 = 135168 (double-buffered cp.async stage)
#define OFF_PQ   204800     // 128 float2 = 1024
#define OFF_MSK  205824     // 2 x 128 f32 = 1024
#define OFF_UV   206848     // 128 float2 = 1024
#define OFF_PART 207872     // 256 f32 = 1024
#define SMEM_PAIR 208896

// ---------------- device scratch ----------------
__device__ float g_scratch_c[8ull  * 1024ull * 128ull];   // [m_block][l][k]
__device__ float g_scratch_r[16ull * 1024ull * 128ull];   // [l_block][m][k]
__device__ float g_catf[1024ull * 1280ull];
__device__ float g_norm_c[1024];
__device__ float g_norm_r[1024];
__device__ float g_u[128];
__device__ float g_v[128];

// ---------------- helpers ----------------
__device__ __forceinline__ void ldsm4(uint32_t &r0, uint32_t &r1, uint32_t &r2, uint32_t &r3, uint32_t addr) {
    asm volatile("ldmatrix.sync.aligned.m8n8.x4.shared.b16 {%0,%1,%2,%3}, [%4];"
                 : "=r"(r0), "=r"(r1), "=r"(r2), "=r"(r3) : "r"(addr));
}
__device__ __forceinline__ void mma_bf16(float* d, uint32_t a0, uint32_t a1, uint32_t a2, uint32_t a3,
                                         uint32_t b0, uint32_t b1) {
    asm volatile("mma.sync.aligned.m16n8k16.row.col.f32.bf16.bf16.f32 "
                 "{%0,%1,%2,%3}, {%4,%5,%6,%7}, {%8,%9}, {%0,%1,%2,%3};"
                 : "+f"(d[0]), "+f"(d[1]), "+f"(d[2]), "+f"(d[3])
                 : "r"(a0), "r"(a1), "r"(a2), "r"(a3), "r"(b0), "r"(b1));
}
__device__ __forceinline__ void mma_tf32(float* d, uint32_t a0, uint32_t a1, uint32_t a2, uint32_t a3,
                                         uint32_t b0, uint32_t b1) {
    asm volatile("mma.sync.aligned.m16n8k8.row.col.f32.tf32.tf32.f32 "
                 "{%0,%1,%2,%3}, {%4,%5,%6,%7}, {%8,%9}, {%0,%1,%2,%3};"
                 : "+f"(d[0]), "+f"(d[1]), "+f"(d[2]), "+f"(d[3])
                 : "r"(a0), "r"(a1), "r"(a2), "r"(a3), "r"(b0), "r"(b1));
}
__device__ __forceinline__ uint32_t f2tf(float f) {
    uint32_t r; asm("cvt.rna.tf32.f32 %0, %1;" : "=r"(r) : "f"(f)); return r;
}
__device__ __forceinline__ uint32_t pack_bf2(float a, float b) {
    __nv_bfloat162 t = __floats2bfloat162_rn(a, b);
    return *reinterpret_cast<uint32_t*>(&t);
}
__device__ __forceinline__ void cpa16(uint32_t dst, const void* src) {
    asm volatile("cp.async.cg.shared.global [%0], [%1], 16;" :: "r"(dst), "l"(src));
}

// ---------------- K0: norms + (u,v) precompute ----------------
__global__ void norm_kernel(const float* __restrict__ mask, const float* __restrict__ w1,
                            const float* __restrict__ lng, const float* __restrict__ lnb,
                            const float* __restrict__ b1) {
    if (blockIdx.x == 8) {          // u[d] = W1[d,:]·g ; v[d] = W1[d,:]·b + b1[d]
        int d = threadIdx.x;
        if (d < 128) {
            const float* wrow = w1 + (size_t)d * 128;
            float u = 0.f, v = 0.f;
#pragma unroll 8
            for (int c = 0; c < 128; c++) {
                float wv = wrow[c];
                u = fmaf(wv, lng[c], u);
                v = fmaf(wv, lnb[c], v);
            }
            g_u[d] = u;
            g_v[d] = v + b1[d];
        }
        return;
    }
    int t = blockIdx.x * 256 + threadIdx.x;
    if (t < 1024) {
        float s = 0.f;
#pragma unroll 8
        for (int l = 0; l < 1024; l++) s += mask[(size_t)l * 1024 + t];
        g_norm_r[t] = s;
    } else {
        int l = t - 1024;
        const float4* p = (const float4*)(mask + (size_t)l * 1024);
        float s = 0.f;
#pragma unroll 8
        for (int m = 0; m < 256; m++) { float4 v = p[m]; s += v.x + v.y + v.z + v.w; }
        g_norm_c[l] = s;
    }
}

// ---------------- K1: pair kernel (HMMA, LN folded, 2m x 4n warp tile, reg reductions) ----------------
__global__ __launch_bounds__(256, 1)
void pair_kernel(const float* __restrict__ z, const float* __restrict__ mask,
                 const float* __restrict__ w1, const float* __restrict__ lng) {
    extern __shared__ char sm[];
    __nv_bfloat16* w1s = (__nv_bfloat16*)(sm + OFF_W1G);
    float*  zstage = (float*)(sm + OFF_Z);
    float2* pqs  = (float2*)(sm + OFF_PQ);
    float*  mskb = (float*)(sm + OFF_MSK);
    float2* uvs  = (float2*)(sm + OFF_UV);
    float*  part = (float*)(sm + OFF_PART);

    const int tid  = threadIdx.x;
    const int w    = tid >> 5;
    const int lane = tid & 31;
    const int g    = lane >> 2;
    const int tc   = lane & 3;
    const int wm   = w >> 2;                // 0..1 : 64-row m-group
    const int wn   = w & 3;                 // 0..3 : 32-col n-group
    const int mb   = blockIdx.x;            // 0..7
    const int lb   = blockIdx.y;            // 0..15
    const int m0   = mb * 128;
    const int r_ld = tid >> 1;              // row 0..127 (copy/convert mapping)
    const int h_ld = tid & 1;               // half-row

    const uint32_t smem_u = (uint32_t)__cvta_generic_to_shared(sm);
    const uint32_t zs_u   = smem_u + OFF_Z;
    const uint32_t msk_u  = smem_u + OFF_MSK;
    const uint32_t at_u   = smem_u + OFF_A;
    const uint32_t w1_u   = smem_u + OFF_W1G;

    // ---- fill W1g tile (bf16, PADA layout, rows = d, cols = c) ----
    for (int i = tid; i < 128 * 128; i += 256) {
        int r = i >> 7, c = i & 127;
        w1s[r * PADA + c] = __float2bfloat16(w1[i] * lng[c]);
    }
    if (tid < 128) uvs[tid] = make_float2(g_u[tid], g_v[tid]);

    // ---- async-copy one l: z tile -> zstage[buf], mask row -> mskb[buf] ----
    auto issue = [&](int l, int buf) {
        const float* zsrc = z + ((size_t)l * 1024 + m0 + r_ld) * 128 + h_ld * 64;
        uint32_t zdst = zs_u + (uint32_t)(buf * (128 * 132 * 4) + (r_ld * 132 + h_ld * 64) * 4);
#pragma unroll
        for (int j = 0; j < 16; j++) cpa16(zdst + j * 16, zsrc + j * 4);
        if (tid < 32) cpa16(msk_u + (uint32_t)(buf * 512 + tid * 16), mask + (size_t)l * 1024 + m0 + tid * 4);
        asm volatile("cp.async.commit_group;");
    };

    issue(lb * LBSZ, 0);

    // per-lane ldmatrix offsets (proven mapping)
    const int lane7 = lane & 7;
    const int a_row = (((lane >> 3) & 1) << 3) + lane7;
    const int a_col = ((lane >> 4) & 1) << 3;
    const int b_row = (((lane >> 4) & 1) << 3) + lane7;
    const int b_col = ((lane >> 3) & 1) << 3;

    __syncthreads();   // W1g + uvs visible

    // ---- preload B fragments for this warp's 32-col n-slice (held all kernel) ----
    // bfr[(k*2 + n16g)*4 + j]: (b0,b1) -> n8 tile 2*n16g, (b2,b3) -> 2*n16g+1
    uint32_t bfr[64];
#pragma unroll
    for (int n16g = 0; n16g < 2; n16g++) {
        uint32_t bb = w1_u + (uint32_t)(((wn * 32 + n16g * 16 + b_row) * PADA + b_col) * 2);
#pragma unroll
        for (int k = 0; k < 8; k++) {
            int o = (k * 2 + n16g) * 4;
            ldsm4(bfr[o], bfr[o + 1], bfr[o + 2], bfr[o + 3], bb + k * 32);
        }
    }

    float acc_l[64];
#pragma unroll
    for (int i = 0; i < 64; i++) acc_l[i] = 0.f;

    for (int i = 0; i < LBSZ; ++i) {
        const int buf = i & 1;
        const int l = lb * LBSZ + i;

        if (i + 1 < LBSZ) {
            issue(l + 1, buf ^ 1);
            asm volatile("cp.async.wait_group 1;");   // copy(i) done (self-copied region)
        } else {
            asm volatile("cp.async.wait_group 0;");
        }

        // ---- convert zstage[buf] -> A (raw bf16, swizzle-free PADA) + row stats ----
        {
            const float* zrow = zstage + (size_t)buf * (128 * 132) + r_ld * 132 + h_ld * 64;
            char* dst = sm + OFF_A + (size_t)(r_ld * PADA + h_ld * 64) * 2;
            float s = 0.f, sq = 0.f;
#pragma unroll
            for (int c4 = 0; c4 < 4; c4++) {
                float4 v0 = *(const float4*)(zrow + c4 * 16);
                float4 v1 = *(const float4*)(zrow + c4 * 16 + 4);
                float4 v2 = *(const float4*)(zrow + c4 * 16 + 8);
                float4 v3 = *(const float4*)(zrow + c4 * 16 + 12);
                s += v0.x + v0.y + v0.z + v0.w + v1.x + v1.y + v1.z + v1.w
                   + v2.x + v2.y + v2.z + v2.w + v3.x + v3.y + v3.z + v3.w;
                sq = fmaf(v0.x, v0.x, sq); sq = fmaf(v0.y, v0.y, sq);
                sq = fmaf(v0.z, v0.z, sq); sq = fmaf(v0.w, v0.w, sq);
                sq = fmaf(v1.x, v1.x, sq); sq = fmaf(v1.y, v1.y, sq);
                sq = fmaf(v1.z, v1.z, sq); sq = fmaf(v1.w, v1.w, sq);
                sq = fmaf(v2.x, v2.x, sq); sq = fmaf(v2.y, v2.y, sq);
                sq = fmaf(v2.z, v2.z, sq); sq = fmaf(v2.w, v2.w, sq);
                sq = fmaf(v3.x, v3.x, sq); sq = fmaf(v3.y, v3.y, sq);
                sq = fmaf(v3.z, v3.z, sq); sq = fmaf(v3.w, v3.w, sq);
                uint4 pk0, pk1;
                pk0.x = pack_bf2(v0.x, v0.y); pk0.y = pack_bf2(v0.z, v0.w);
                pk0.z = pack_bf2(v1.x, v1.y); pk0.w = pack_bf2(v1.z, v1.w);
                pk1.x = pack_bf2(v2.x, v2.y); pk1.y = pack_bf2(v2.z, v2.w);
                pk1.z = pack_bf2(v3.x, v3.y); pk1.w = pack_bf2(v3.z, v3.w);
                *(uint4*)(dst + c4 * 32)      = pk0;
                *(uint4*)(dst + c4 * 32 + 16) = pk1;
            }
            s  += __shfl_xor_sync(0xffffffffu, s, 1);
            sq += __shfl_xor_sync(0xffffffffu, sq, 1);
            float mu  = s * (1.f / 128.f);
            float var = fmaf(sq, 1.f / 128.f, -mu * mu);
            float rs  = rsqrtf(var + 1e-5f);
            if (h_ld == 0) pqs[r_ld] = make_float2(rs, rs * mu);
        }
        __syncthreads();   // barrier#1: A + pqs + mask(buf) visible

        // ---- GEMM: warp tile 64 rows (wm) x 32 cols (wn) ----
        float acc[64];
#pragma unroll
        for (int j = 0; j < 64; j++) acc[j] = 0.f;
#pragma unroll
        for (int mt = 0; mt < 4; mt++) {
            uint32_t abase = at_u + (uint32_t)(((wm * 64 + mt * 16 + a_row) * PADA + a_col) * 2);
#pragma unroll
            for (int k = 0; k < 8; k++) {
                uint32_t a0, a1, a2, a3;
                ldsm4(a0, a1, a2, a3, abase + k * 32);
#pragma unroll
                for (int nt = 0; nt < 4; nt++) {
                    int bo = (k * 2 + (nt >> 1)) * 4 + (nt & 1) * 2;
                    mma_bf16(acc + (mt * 4 + nt) * 4, a0, a1, a2, a3, bfr[bo], bfr[bo + 1]);
                }
            }
        }

        // ---- epilogue: y = p*G - q*u + v ; relu ; *mask ; acc_l += ; reg colsum ----
        float cs[8];
#pragma unroll
        for (int j = 0; j < 8; j++) cs[j] = 0.f;
#pragma unroll
        for (int mt = 0; mt < 4; mt++) {
            int rlo = wm * 64 + mt * 16 + g, rhi = rlo + 8;
            float2 pq0 = pqs[rlo], pq1 = pqs[rhi];
            float mk0 = mskb[buf * 128 + rlo], mk1 = mskb[buf * 128 + rhi];
#pragma unroll
            for (int nt = 0; nt < 4; nt++) {
                int c0 = wn * 32 + nt * 8 + tc * 2;
                float2 uvA = uvs[c0], uvB = uvs[c0 + 1];
                int id = (mt * 4 + nt) * 4;
                float t0 = fmaxf(fmaf(pq0.x, acc[id],     fmaf(-pq0.y, uvA.x, uvA.y)), 0.f) * mk0;
                float t1 = fmaxf(fmaf(pq0.x, acc[id + 1], fmaf(-pq0.y, uvB.x, uvB.y)), 0.f) * mk0;
                float t2 = fmaxf(fmaf(pq1.x, acc[id + 2], fmaf(-pq1.y, uvA.x, uvA.y)), 0.f) * mk1;
                float t3 = fmaxf(fmaf(pq1.x, acc[id + 3], fmaf(-pq1.y, uvB.x, uvB.y)), 0.f) * mk1;
                acc_l[id] += t0; acc_l[id + 1] += t1; acc_l[id + 2] += t2; acc_l[id + 3] += t3;
                cs[nt * 2]     += t0 + t2;
                cs[nt * 2 + 1] += t1 + t3;
            }
        }
        // reduce colsum over g (lane bits 2..4); lanes 0..3 end with full 64-row sums
#pragma unroll
        for (int j = 0; j < 8; j++) {
            cs[j] += __shfl_xor_sync(0xffffffffu, cs[j], 4);
            cs[j] += __shfl_xor_sync(0xffffffffu, cs[j], 8);
            cs[j] += __shfl_xor_sync(0xffffffffu, cs[j], 16);
        }
        if (lane < 4) {
#pragma unroll
            for (int nt = 0; nt < 4; nt++)
                *(float2*)&part[wm * 128 + wn * 32 + nt * 8 + tc * 2] = make_float2(cs[nt * 2], cs[nt * 2 + 1]);
        }
        __syncthreads();   // barrier#2: part complete; A reads done

        if (tid < 128)
            g_scratch_c[((size_t)mb * 1024 + l) * 128 + tid] = part[tid] + part[128 + tid];
    }

    // ---- over-l partials -> g_scratch_r ----
#pragma unroll
    for (int mt = 0; mt < 4; mt++) {
        int rl = m0 + wm * 64 + mt * 16 + g;
#pragma unroll
        for (int nt = 0; nt < 4; nt++) {
            int c0 = wn * 32 + nt * 8 + tc * 2;
            int id = (mt * 4 + nt) * 4;
            *(float2*)&g_scratch_r[((size_t)lb * 1024 + rl)     * 128 + c0] =
                make_float2(acc_l[id], acc_l[id + 1]);
            *(float2*)&g_scratch_r[((size_t)lb * 1024 + rl + 8) * 128 + c0] =
                make_float2(acc_l[id + 2], acc_l[id + 3]);
        }
    }
}

// ---------------- K2: reduce partials, deferred GEMM2, build concat ----------------
__global__ __launch_bounds__(256, 4)
void cat_kernel(const float* __restrict__ s_s_in, const float* __restrict__ w2,
                const float* __restrict__ b2) {
    __shared__ alignas(16) float Sc[128];
    __shared__ alignas(16) float Sr[128];
    int l = blockIdx.x;
    int t = threadIdx.x;
    if (t < 128) {
        float s = 0.f;
#pragma unroll
        for (int p = 0; p < 8; p++) s += g_scratch_c[((size_t)p * 1024 + l) * 128 + t];
        Sc[t] = s;
    } else {
        int c = t - 128;
        float s = 0.f;
#pragma unroll
        for (int p = 0; p < 16; p++) s += g_scratch_r[((size_t)p * 1024 + l) * 128 + c];
        Sr[c] = s;
    }
    __syncthreads();

    int c = t & 127;
    const float4* wrow = (const float4*)(w2 + (size_t)c * 128);
    const float4* Sv   = (const float4*)((t < 128) ? Sc : Sr);
    float s = 0.f;
#pragma unroll 8
    for (int kk = 0; kk < 32; kk++) {
        float4 wv = wrow[kk], sv = Sv[kk];
        s = fmaf(wv.x, sv.x, s); s = fmaf(wv.y, sv.y, s);
        s = fmaf(wv.z, sv.z, s); s = fmaf(wv.w, sv.w, s);
    }
    float ns = (t < 128) ? g_norm_c[l] : g_norm_r[l];
    float val = (s + ns * b2[c]) / fmaxf(ns, 1.f);
    g_catf[(size_t)l * 1280 + ((t < 128) ? 0 : 128) + c] = val;

    for (int cc = t; cc < 1024; cc += 256)
        g_catf[(size_t)l * 1280 + 256 + cc] = s_s_in[(size_t)l * 1024 + cc];
}

// ---------------- K3: final projection (tf32), 64x128 tiles (R6-measured 36us version) ----------------
#define PADF 36
__global__ __launch_bounds__(256, 2)
void final_gemm(const float* __restrict__ wc, const float* __restrict__ bc, float* __restrict__ out) {
    __shared__ uint32_t atf[64 * PADF];
    __shared__ uint32_t btf[128 * PADF];
    const int tid = threadIdx.x, w = tid >> 5, lane = tid & 31;
    const int g = lane >> 2, tc = lane & 3;
    const int wr = w & 3, cg = w >> 2;
    const int l0 = blockIdx.y * 64, d0 = blockIdx.x * 128;
    const int q = tid & 7, rload = tid >> 3;

    float d[32];
#pragma unroll
    for (int i = 0; i < 32; i++) d[i] = 0.f;

    float4 va0, va1, vb0, vb1, vb2, vb3;
    auto ldg = [&](int kc) {
        int k0 = kc * 32 + q * 4;
        va0 = *(const float4*)(g_catf + (size_t)(l0 + rload)      * 1280 + k0);
        va1 = *(const float4*)(g_catf + (size_t)(l0 + rload + 32) * 1280 + k0);
        vb0 = *(const float4*)(wc + (size_t)(d0 + rload)      * 1280 + k0);
        vb1 = *(const float4*)(wc + (size_t)(d0 + rload + 32) * 1280 + k0);
        vb2 = *(const float4*)(wc + (size_t)(d0 + rload + 64) * 1280 + k0);
        vb3 = *(const float4*)(wc + (size_t)(d0 + rload + 96) * 1280 + k0);
    };
    auto stv = [&](uint32_t* base, int r, float4 v) {
        uint32_t* p = base + r * PADF + q;
        p[0] = f2tf(v.x); p[8] = f2tf(v.y); p[16] = f2tf(v.z); p[24] = f2tf(v.w);
    };

    ldg(0);
    for (int kc = 0; kc < 40; ++kc) {
        __syncthreads();
        stv(atf, rload,      va0); stv(atf, rload + 32, va1);
        stv(btf, rload,      vb0); stv(btf, rload + 32, vb1);
        stv(btf, rload + 64, vb2); stv(btf, rload + 96, vb3);
        if (kc + 1 < 40) ldg(kc + 1);
        __syncthreads();

        uint32_t aw0[8], aw1[8];
        *(uint4*)(aw0)     = *(uint4*)&atf[(16 * wr + g)     * PADF + tc * 8];
        *(uint4*)(aw0 + 4) = *(uint4*)&atf[(16 * wr + g)     * PADF + tc * 8 + 4];
        *(uint4*)(aw1)     = *(uint4*)&atf[(16 * wr + 8 + g) * PADF + tc * 8];
        *(uint4*)(aw1 + 4) = *(uint4*)&atf[(16 * wr + 8 + g) * PADF + tc * 8 + 4];
#pragma unroll
        for (int nt = 0; nt < 8; nt++) {
            int rowb = cg * 64 + nt * 8 + g;
            uint32_t bw[8];
            *(uint4*)(bw)     = *(uint4*)&btf[rowb * PADF + tc * 8];
            *(uint4*)(bw + 4) = *(uint4*)&btf[rowb * PADF + tc * 8 + 4];
#pragma unroll
            for (int kp = 0; kp < 4; kp++)
                mma_tf32(d + nt * 4, aw0[2 * kp], aw1[2 * kp], aw0[2 * kp + 1], aw1[2 * kp + 1],
                         bw[2 * kp], bw[2 * kp + 1]);
        }
    }

    int row = l0 + 16 * wr + g;
#pragma unroll
    for (int nt = 0; nt < 8; nt++) {
        int col = d0 + cg * 64 + nt * 8 + tc * 2;
        float bb0 = bc[col], bb1 = bc[col + 1];
        *(float2*)&out[(size_t)row * 1024 + col]       = make_float2(d[nt * 4 + 0] + bb0, d[nt * 4 + 1] + bb1);
        *(float2*)&out[(size_t)(row + 8) * 1024 + col] = make_float2(d[nt * 4 + 2] + bb0, d[nt * 4 + 3] + bb1);
    }
}

// ---------------- launch ----------------
extern "C" void kernel_launch(void* const* d_in, const int* in_sizes, int n_in,
                              void* d_out, int out_size) {
    const float* s_z    = (const float*)d_in[0];
    const float* s_s_in = (const float*)d_in[1];
    const float* mask   = (const float*)d_in[2];
    const float* ln_g   = (const float*)d_in[3];
    const float* ln_b   = (const float*)d_in[4];
    const float* w1     = (const float*)d_in[5];
    const float* b1     = (const float*)d_in[6];
    const float* w2     = (const float*)d_in[7];
    const float* b2     = (const float*)d_in[8];
    const float* wc     = (const float*)d_in[9];
    const float* bc     = (const float*)d_in[10];
    float* out = (float*)d_out;

    cudaFuncSetAttribute(pair_kernel, cudaFuncAttributeMaxDynamicSharedMemorySize, SMEM_PAIR);

    norm_kernel<<<9, 256>>>(mask, w1, ln_g, ln_b, b1);
    pair_kernel<<<dim3(8, NLB), 256, SMEM_PAIR>>>(s_z, mask, w1, ln_g);
    cat_kernel<<<1024, 256>>>(s_s_in, w2, b2);
    final_gemm<<<dim3(8, 16), 256>>>(wc, bc, out);
}